// round 14
// baseline (speedup 1.0000x reference)
#include <cuda_runtime.h>
#include <cuda_fp16.h>
#include <math.h>

#define NB 64
#define NL 1024
#define ND 1024
#define SPLIT 32               // l-splits for column passes (CH = 32)
#define CH (NL / SPLIT)
#define EPSF 1e-15f
#define PROJ_EPS 4e-3f

// ---------------- scratch (device globals) ----------------
__device__ float g_combined[NB * 2 * ND];   // [b,0:D)=mixl, [b,D:2D)=q
__device__ float g_scores[NB * NL];
__device__ float g_aw[NB * NL];
__device__ float g_bt[NB * NL];
__device__ float g_btn[NB];
__device__ float g_u[NB * ND];
__device__ float g_v[NB * ND];
__device__ float g_dl[NB * ND];
__device__ float g_lam[NB * NL];
__device__ float g_part[6 * NB * SPLIT * ND];    // kD partials; kN reuses arrays 0..2
__device__ __half g_ctxh[(size_t)NB * NL * ND];  // fp16 shadow of ctx (128 MB)

__device__ __forceinline__ float artanh_c(float x) {
    x = fminf(fmaxf(x, -1.0f + 1e-7f), 1.0f - 1e-7f);
    return atanhf(x);
}

// fast block reduction for 1024 threads: warp shuffle + 32-slot smem
__device__ __forceinline__ float bsum1024(float v, float* s32) {
    int lane = threadIdx.x & 31, warp = threadIdx.x >> 5;
#pragma unroll
    for (int o = 16; o > 0; o >>= 1) v += __shfl_xor_sync(0xffffffffu, v, o);
    if (lane == 0) s32[warp] = v;
    __syncthreads();
    if (warp == 0) {
        float w = s32[lane];
#pragma unroll
        for (int o = 16; o > 0; o >>= 1) w += __shfl_xor_sync(0xffffffffu, w, o);
        if (lane == 0) s32[0] = w;
    }
    __syncthreads();
    float r = s32[0];
    __syncthreads();
    return r;
}

__device__ __forceinline__ float bmax1024(float v, float* s32) {
    int lane = threadIdx.x & 31, warp = threadIdx.x >> 5;
#pragma unroll
    for (int o = 16; o > 0; o >>= 1) v = fmaxf(v, __shfl_xor_sync(0xffffffffu, v, o));
    if (lane == 0) s32[warp] = v;
    __syncthreads();
    if (warp == 0) {
        float w = s32[lane];
#pragma unroll
        for (int o = 16; o > 0; o >>= 1) w = fmaxf(w, __shfl_xor_sync(0xffffffffu, w, o));
        if (lane == 0) s32[0] = w;
    }
    __syncthreads();
    float r = s32[0];
    __syncthreads();
    return r;
}

// ---------------- A: q = query @ W_in^T ----------------
__global__ void kA(const float* __restrict__ query, const float* __restrict__ W_in) {
    int b = threadIdx.x;
    int e = blockIdx.x * 4 + threadIdx.y;
    const float4* q4 = (const float4*)(query + (size_t)b * ND);
    const float4* w4 = (const float4*)(W_in + (size_t)e * ND);
    float acc = 0.f;
#pragma unroll 4
    for (int k = 0; k < ND / 4; k++) {
        float4 a = q4[k], w = w4[k];
        acc += a.x * w.x + a.y * w.y + a.z * w.z + a.w * w.w;
    }
    g_combined[(size_t)b * 2 * ND + ND + e] = acc;
}

// ---------------- B: scores + fp16 shadow write  (ascending b) ----------------
__global__ void kB(const float* __restrict__ ctx) {
    __shared__ float sq[ND];
    int b = blockIdx.y;
    int warp = threadIdx.x >> 5, lane = threadIdx.x & 31;
    ((float4*)sq)[threadIdx.x] = ((const float4*)(g_combined + (size_t)b * 2 * ND + ND))[threadIdx.x];
    __syncthreads();
    int l = blockIdx.x * 8 + warp;
    size_t row = ((size_t)(b * NL + l)) * ND;
    const float4* c4 = (const float4*)(ctx + row);
    uint2* h2 = (uint2*)(g_ctxh + row);          // uint2 = 4 halves
    const float4* s4 = (const float4*)sq;
    float acc = 0.f;
#pragma unroll
    for (int k = 0; k < 8; k++) {
        int i = k * 32 + lane;
        float4 cv = c4[i], qv = s4[i];
        acc += cv.x * qv.x + cv.y * qv.y + cv.z * qv.z + cv.w * qv.w;
        union { __half2 h[2]; uint2 u; } pk;
        pk.h[0] = __floats2half2_rn(cv.x, cv.y);
        pk.h[1] = __floats2half2_rn(cv.z, cv.w);
        h2[i] = pk.u;
    }
#pragma unroll
    for (int o = 16; o > 0; o >>= 1) acc += __shfl_down_sync(0xffffffffu, acc, o);
    if (lane == 0) g_scores[b * NL + l] = acc;
}

// ---------------- C: softmax + expmap0/project (aw), bt ----------------
__global__ void kC(const float* __restrict__ dt, const float* __restrict__ cp,
                   const float* __restrict__ ab, float* __restrict__ out_aw) {
    __shared__ float s32[32];
    int b = blockIdx.x, t = threadIdx.x;
    float c = cp[0], sc = sqrtf(c);
    float maxn = (1.0f - PROJ_EPS) / sc;

    float s = g_scores[b * NL + t];
    float mx = bmax1024(s, s32);
    float e = expf(s - mx);
    float sum = bsum1024(e, s32);
    float aw = e / sum;

    float n = fmaxf(sqrtf(bsum1024(aw * aw, s32)), EPSF);
    float awh = tanhf(sc * n) / (sc * n) * aw;
    float nh = fmaxf(sqrtf(bsum1024(awh * awh, s32)), EPSF);
    if (nh > maxn) awh *= maxn / nh;
    g_aw[b * NL + t] = awh;
    out_aw[b * NL + t] = awh;

    float braw = expf(-ab[b] * dt[b * NL + t]);
    float bn = fmaxf(sqrtf(bsum1024(braw * braw, s32)), EPSF);
    float bth = tanhf(sc * bn) / (sc * bn) * braw;
    float bh = fmaxf(sqrtf(bsum1024(bth * bth, s32)), EPSF);
    if (bh > maxn) bth *= maxn / bh;
    g_bt[b * NL + t] = bth;
    if (t == 0) g_btn[b] = fminf(bh, maxn);
}

// ---------------- D1: partial column stats from fp16 ctx (512 thr x half2, descending b) ----
__global__ void __launch_bounds__(512) kD1() {
    __shared__ float sc1[CH], sc2[CH], sc3[CH];
    int b = NB - 1 - blockIdx.y;       // reverse: reuse L2 tail from kB
    int s = blockIdx.x, t = threadIdx.x;
    int l0 = s * CH;
    if (t < CH) {
        float a = g_aw[b * NL + l0 + t];
        float bt = g_bt[b * NL + l0 + t];
        float a2 = a * a;
        sc1[t] = a2;
        sc2[t] = a2 * bt * bt;
        sc3[t] = a2 * bt;
    }
    __syncthreads();
    const __half2* cb = (const __half2*)(g_ctxh + ((size_t)(b * NL + l0)) * ND) + t;

    float2 sx2 = {0,0}, swx2 = {0,0};
    float2 s2p = {0,0}, s2n = {0,0}, sxp = {0,0}, sxn = {0,0};

#pragma unroll 4
    for (int ll = 0; ll < CH; ll++) {
        float2 x = __half22float2(cb[(size_t)ll * (ND / 2)]);
        float c1 = sc1[ll], c2 = sc2[ll], c3 = sc3[ll];
        {
            float x2 = x.x * x.x; float xp = (x.x > 0.f) ? x2 : 0.f; float xm = x2 - xp;
            sx2.x += x2; swx2.x = fmaf(c1, x2, swx2.x);
            s2p.x = fmaf(c2, xp, s2p.x); s2n.x = fmaf(c2, xm, s2n.x);
            sxp.x = fmaf(c3, xp, sxp.x); sxn.x = fmaf(c3, xm, sxn.x);
        }
        {
            float x2 = x.y * x.y; float xp = (x.y > 0.f) ? x2 : 0.f; float xm = x2 - xp;
            sx2.y += x2; swx2.y = fmaf(c1, x2, swx2.y);
            s2p.y = fmaf(c2, xp, s2p.y); s2n.y = fmaf(c2, xm, s2n.y);
            sxp.y = fmaf(c3, xp, sxp.y); sxn.y = fmaf(c3, xm, sxn.y);
        }
    }
    size_t base = ((size_t)(b * SPLIT + s)) * ND;
    size_t stride = (size_t)NB * SPLIT * ND;
    ((float2*)(g_part + 0 * stride + base))[t] = sx2;
    ((float2*)(g_part + 1 * stride + base))[t] = swx2;
    ((float2*)(g_part + 2 * stride + base))[t] = s2p;
    ((float2*)(g_part + 3 * stride + base))[t] = s2n;
    ((float2*)(g_part + 4 * stride + base))[t] = sxp;
    ((float2*)(g_part + 5 * stride + base))[t] = sxn;
}

// ---------------- Df: finalize per-(b,d) scalars u, v, delta ----------------
__global__ void kDf(const float* __restrict__ cp, const float* __restrict__ ae) {
    int b = blockIdx.y;
    int d = blockIdx.x * 256 + threadIdx.x;
    size_t stride = (size_t)NB * SPLIT * ND;
    float sx2 = 0.f, swx2 = 0.f, s2p = 0.f, s2n = 0.f, sxp = 0.f, sxn = 0.f;
#pragma unroll
    for (int s = 0; s < SPLIT; s++) {
        size_t base = ((size_t)(b * SPLIT + s)) * ND + d;
        sx2  += g_part[0 * stride + base];
        swx2 += g_part[1 * stride + base];
        s2p  += g_part[2 * stride + base];
        s2n  += g_part[3 * stride + base];
        sxp  += g_part[4 * stride + base];
        sxn  += g_part[5 * stride + base];
    }

    float c = cp[0], sc = sqrtf(c);
    float maxn = (1.0f - PROJ_EPS) / sc;

    float xn   = fmaxf(sqrtf(sx2), EPSF);
    float wxnr = sqrtf(swx2);
    float wxn  = fmaxf(wxnr, EPSF);
    float s1 = tanhf(wxn / xn * artanh_c(sc * xn)) / (wxn * sc);
    float n1 = fmaxf(fabsf(s1) * wxnr, EPSF);
    float alpha = s1 * (n1 > maxn ? maxn / n1 : 1.0f);
    float nmixr = fabsf(alpha) * wxnr;

    float aeb = ae[b];
    float xn7 = fmaxf(nmixr, EPSF);
    float wxn7 = fmaxf(fabsf(aeb) * nmixr, EPSF);
    float t7 = tanhf(wxn7 / xn7 * artanh_c(sc * xn7)) / (wxn7 * sc);
    float n7 = fmaxf(fabsf(t7 * aeb) * nmixr, EPSF);
    float T = t7 * aeb * alpha * (n7 > maxn ? maxn / n7 : 1.0f);

    float m8r = sqrtf(s2p + s2n);
    float xn8 = g_btn[b];
    float wxn8 = fmaxf(fabsf(T) * m8r, EPSF);
    float t8 = tanhf(wxn8 / xn8 * artanh_c(sc * xn8)) / (wxn8 * sc);
    float dpre = t8 * T;
    float n8 = fmaxf(fabsf(dpre) * m8r, EPSF);
    float dl = dpre * (n8 > maxn ? maxn / n8 : 1.0f);

    float x2 = alpha * alpha * swx2;
    bool pos = (dl > 0.f);
    float S2 = pos ? s2p : s2n;
    float SX = pos ? sxp : sxn;
    float y2 = dl * dl * S2;
    float xy = alpha * dl * SX;
    float A  = 1.0f + 2.0f * c * xy + c * y2;
    float Bc = 1.0f - c * x2;
    float den = fmaxf(1.0f + 2.0f * c * xy + c * c * x2 * y2, EPSF);
    float nn2 = (A * A * x2 + 2.0f * A * Bc * xy + Bc * Bc * y2) / (den * den);
    float n10 = fmaxf(sqrtf(fmaxf(nn2, 0.f)), EPSF);
    float p10 = (n10 > maxn) ? maxn / n10 : 1.0f;

    g_u[b * ND + d]  = p10 * A * alpha / den;
    g_v[b * ND + d]  = p10 * Bc * dl / den;
    g_dl[b * ND + d] = dl;
}

// ---------------- P: lambda row pass — warp-per-row, BARRIER-FREE stream (ascending b) ----
// Sum_d m^2 = a^2 * [ sum u^2 x^2 + (2 bt uv + bt^2 v^2) * x^2 * 1(x*sgn(dl)>0) ]
// Per-lane combine -> ONE shuffle reduce per row. 512 thr = 16 warps, 32 rows/block.
__global__ void __launch_bounds__(512) kP(const float* __restrict__ cp) {
    __shared__ float4 sw[ND];            // (u^2, u*v, v^2, sgn(dl)) -> 16 KB
    __shared__ float saw[32], sbt[32];
    int b = blockIdx.y;                  // ascending: reuse L2 tail from kD1
    int t = threadIdx.x;
    int warp = t >> 5, lane = t & 31;
    int l0 = blockIdx.x * 32;
    float c = cp[0];

    for (int d = t; d < ND; d += 512) {
        float u = g_u[b * ND + d], v = g_v[b * ND + d], dl = g_dl[b * ND + d];
        sw[d] = make_float4(u * u, u * v, v * v, (dl > 0.f) ? 1.f : -1.f);
    }
    if (t < 32) { saw[t] = g_aw[b * NL + l0 + t]; sbt[t] = g_bt[b * NL + l0 + t]; }
    __syncthreads();

#pragma unroll
    for (int rr = 0; rr < 2; rr++) {
        int r = warp + rr * 16;
        int l = l0 + r;
        float a = saw[r], bt = sbt[r];
        float bt2 = bt * bt, twobt = 2.f * bt;
        const uint2* row = (const uint2*)(g_ctxh + ((size_t)(b * NL + l)) * ND);
        float ss = 0.f;
#pragma unroll
        for (int k = 0; k < 8; k++) {
            int i = k * 32 + lane;               // covers 4 d's: 4i..4i+3
            uint2 xx = row[i];
            float2 x01 = __half22float2(*(__half2*)&xx.x);
            float2 x23 = __half22float2(*(__half2*)&xx.y);
            float4 w0 = sw[4 * i + 0];
            float4 w1 = sw[4 * i + 1];
            float4 w2 = sw[4 * i + 2];
            float4 w3 = sw[4 * i + 3];
            {
                float x2 = x01.x * x01.x; float xm = (x01.x * w0.w > 0.f) ? x2 : 0.f;
                float K = fmaf(bt2, w0.z, twobt * w0.y);
                ss = fmaf(w0.x, x2, ss); ss = fmaf(K, xm, ss);
            }
            {
                float x2 = x01.y * x01.y; float xm = (x01.y * w1.w > 0.f) ? x2 : 0.f;
                float K = fmaf(bt2, w1.z, twobt * w1.y);
                ss = fmaf(w1.x, x2, ss); ss = fmaf(K, xm, ss);
            }
            {
                float x2 = x23.x * x23.x; float xm = (x23.x * w2.w > 0.f) ? x2 : 0.f;
                float K = fmaf(bt2, w2.z, twobt * w2.y);
                ss = fmaf(w2.x, x2, ss); ss = fmaf(K, xm, ss);
            }
            {
                float x2 = x23.y * x23.y; float xm = (x23.y * w3.w > 0.f) ? x2 : 0.f;
                float K = fmaf(bt2, w3.z, twobt * w3.y);
                ss = fmaf(w3.x, x2, ss); ss = fmaf(K, xm, ss);
            }
        }
#pragma unroll
        for (int o = 16; o > 0; o >>= 1) ss += __shfl_xor_sync(0xffffffffu, ss, o);
        if (lane == 0)
            g_lam[b * NL + l] = 2.0f / fmaxf(1.0f - c * (a * a * ss), EPSF);
    }
}

// ---------------- N: nom column pass — 3 accumulators, barrier-free (descending b) --------
// S1 = sum lam*a*x ; S2p/S2n = sum lam*a*bt*x split by sign(x).
__global__ void __launch_bounds__(512) kN() {
    __shared__ float sc1[CH], sc2[CH];
    int b = NB - 1 - blockIdx.y;        // reverse: reuse L2 tail from kP
    int s = blockIdx.x, t = threadIdx.x;
    int l0 = s * CH;
    if (t < CH) {
        float lam = g_lam[b * NL + l0 + t];
        float a = g_aw[b * NL + l0 + t];
        float bt = g_bt[b * NL + l0 + t];
        sc1[t] = lam * a;
        sc2[t] = lam * a * bt;
    }
    __syncthreads();
    const __half2* cb = (const __half2*)(g_ctxh + ((size_t)(b * NL + l0)) * ND) + t;

    float2 S1 = {0,0}, S2p = {0,0}, S2n = {0,0};
#pragma unroll 4
    for (int ll = 0; ll < CH; ll++) {
        float2 x = __half22float2(cb[(size_t)ll * (ND / 2)]);
        float c1 = sc1[ll], c2 = sc2[ll];
        {
            float xp = (x.x > 0.f) ? x.x : 0.f; float xm = x.x - xp;
            S1.x = fmaf(c1, x.x, S1.x); S2p.x = fmaf(c2, xp, S2p.x); S2n.x = fmaf(c2, xm, S2n.x);
        }
        {
            float xp = (x.y > 0.f) ? x.y : 0.f; float xm = x.y - xp;
            S1.y = fmaf(c1, x.y, S1.y); S2p.y = fmaf(c2, xp, S2p.y); S2n.y = fmaf(c2, xm, S2n.y);
        }
    }
    size_t base = ((size_t)(b * SPLIT + s)) * ND;
    size_t stride = (size_t)NB * SPLIT * ND;
    ((float2*)(g_part + 0 * stride + base))[t] = S1;
    ((float2*)(g_part + 1 * stride + base))[t] = S2p;
    ((float2*)(g_part + 2 * stride + base))[t] = S2n;
}

// ---------------- F: midpoint epilogue (combines nom partials) ----------------
__global__ void kF(const float* __restrict__ cp) {
    __shared__ float s32[32];
    int b = blockIdx.x, t = threadIdx.x;
    float c = cp[0], sc = sqrtf(c);
    float lam = g_lam[b * NL + t];
    float den = bsum1024(lam - 1.0f, s32);
    den = (den >= 0.f) ? fmaxf(den, 1e-10f) : fminf(den, -1e-10f);

    size_t stride = (size_t)NB * SPLIT * ND;
    float S1 = 0.f, S2p = 0.f, S2n = 0.f;
#pragma unroll
    for (int s = 0; s < SPLIT; s++) {
        size_t base = ((size_t)(b * SPLIT + s)) * ND + t;
        S1  += g_part[0 * stride + base];
        S2p += g_part[1 * stride + base];
        S2n += g_part[2 * stride + base];
    }
    float u = g_u[b * ND + t], v = g_v[b * ND + t], dl = g_dl[b * ND + t];
    float nom = u * S1 + v * ((dl > 0.f) ? S2p : S2n);

    float tm = nom / den;
    float nr = sqrtf(bsum1024(tm * tm, s32));
    float n = fmaxf(nr, EPSF);
    float cf = tanhf(0.5f * artanh_c(sc * n)) / (sc * n);
    float nf = fmaxf(fabsf(cf) * nr, EPSF);
    float lc = artanh_c(sc * nf) / (sc * nf);
    g_combined[(size_t)b * 2 * ND + t] = lc * cf * tm;
}

// ---------------- G: out = tanh(combined @ W_out^T) ----------------
__global__ void kG(const float* __restrict__ W_out, float* __restrict__ out) {
    int b = threadIdx.x;
    int d = blockIdx.x * 4 + threadIdx.y;
    const float4* cb4 = (const float4*)(g_combined + (size_t)b * 2 * ND);
    const float4* w4  = (const float4*)(W_out + (size_t)d * 2 * ND);
    float acc = 0.f;
#pragma unroll 4
    for (int k = 0; k < 2 * ND / 4; k++) {
        float4 a = cb4[k], w = w4[k];
        acc += a.x * w.x + a.y * w.y + a.z * w.z + a.w * w.w;
    }
    out[b * ND + d] = tanhf(acc);
}

// ---------------- launch ----------------
extern "C" void kernel_launch(void* const* d_in, const int* in_sizes, int n_in,
                              void* d_out, int out_size) {
    const float* query = (const float*)d_in[0];
    const float* ctx   = (const float*)d_in[1];
    const float* dt    = (const float*)d_in[2];
    const float* cp    = (const float*)d_in[3];
    const float* W_in  = (const float*)d_in[4];
    const float* W_out = (const float*)d_in[5];
    const float* ae    = (const float*)d_in[6];
    const float* ab    = (const float*)d_in[7];
    float* out = (float*)d_out;

    kA <<<ND / 4, dim3(64, 4)>>>(query, W_in);
    kB <<<dim3(NL / 8, NB), 256>>>(ctx);
    kC <<<NB, 1024>>>(dt, cp, ab, out + NB * ND);
    kD1<<<dim3(SPLIT, NB), 512>>>();
    kDf<<<dim3(ND / 256, NB), 256>>>(cp, ae);
    kP <<<dim3(NL / 32, NB), 512>>>(cp);
    kN <<<dim3(SPLIT, NB), 512>>>();
    kF <<<NB, 1024>>>(cp);
    kG <<<ND / 4, dim3(64, 4)>>>(W_out, out);
}

// round 15
// speedup vs baseline: 1.8331x; 1.8331x over previous
#include <cuda_runtime.h>
#include <cuda_fp16.h>
#include <math.h>

#define NB 64
#define NL 1024
#define ND 1024
#define SPLIT 32               // kD l-splits (CH_D = 32)
#define CH_D (NL / SPLIT)
#define SPLITE 32              // kE l-splits (CH_E = 32)
#define CH_E (NL / SPLITE)
#define EPSF 1e-15f
#define PROJ_EPS 4e-3f

// ---------------- scratch (device globals) ----------------
__device__ float g_combined[NB * 2 * ND];   // [b,0:D)=mixl, [b,D:2D)=q
__device__ float g_scores[NB * NL];
__device__ float g_aw[NB * NL];
__device__ float g_bt[NB * NL];
__device__ float g_btn[NB];
__device__ float g_u[NB * ND];
__device__ float g_v[NB * ND];
__device__ float g_dl[NB * ND];
__device__ float g_lam[NB * NL];
__device__ float g_part[6 * NB * SPLIT * ND];    // kD partials: [k][b][s][d]
__device__ float g_nomp[NB * SPLITE * ND];       // kE nom partials
__device__ __half g_ctxh[(size_t)NB * NL * ND];  // fp16 shadow of ctx (128 MB)

__device__ __forceinline__ float artanh_c(float x) {
    x = fminf(fmaxf(x, -1.0f + 1e-7f), 1.0f - 1e-7f);
    return atanhf(x);
}

// fast block reduction for 1024 threads: warp shuffle + 32-slot smem
__device__ __forceinline__ float bsum1024(float v, float* s32) {
    int lane = threadIdx.x & 31, warp = threadIdx.x >> 5;
#pragma unroll
    for (int o = 16; o > 0; o >>= 1) v += __shfl_xor_sync(0xffffffffu, v, o);
    if (lane == 0) s32[warp] = v;
    __syncthreads();
    if (warp == 0) {
        float w = s32[lane];
#pragma unroll
        for (int o = 16; o > 0; o >>= 1) w += __shfl_xor_sync(0xffffffffu, w, o);
        if (lane == 0) s32[0] = w;
    }
    __syncthreads();
    float r = s32[0];
    __syncthreads();
    return r;
}

__device__ __forceinline__ float bmax1024(float v, float* s32) {
    int lane = threadIdx.x & 31, warp = threadIdx.x >> 5;
#pragma unroll
    for (int o = 16; o > 0; o >>= 1) v = fmaxf(v, __shfl_xor_sync(0xffffffffu, v, o));
    if (lane == 0) s32[warp] = v;
    __syncthreads();
    if (warp == 0) {
        float w = s32[lane];
#pragma unroll
        for (int o = 16; o > 0; o >>= 1) w = fmaxf(w, __shfl_xor_sync(0xffffffffu, w, o));
        if (lane == 0) s32[0] = w;
    }
    __syncthreads();
    float r = s32[0];
    __syncthreads();
    return r;
}

// ---------------- A: q = query @ W_in^T ----------------
__global__ void kA(const float* __restrict__ query, const float* __restrict__ W_in) {
    int b = threadIdx.x;
    int e = blockIdx.x * 4 + threadIdx.y;
    const float4* q4 = (const float4*)(query + (size_t)b * ND);
    const float4* w4 = (const float4*)(W_in + (size_t)e * ND);
    float acc = 0.f;
#pragma unroll 4
    for (int k = 0; k < ND / 4; k++) {
        float4 a = q4[k], w = w4[k];
        acc += a.x * w.x + a.y * w.y + a.z * w.z + a.w * w.w;
    }
    g_combined[(size_t)b * 2 * ND + ND + e] = acc;
}

// ---------------- B: scores + fp16 shadow write  (ascending b) ----------------
__global__ void kB(const float* __restrict__ ctx) {
    __shared__ float sq[ND];
    int b = blockIdx.y;
    int warp = threadIdx.x >> 5, lane = threadIdx.x & 31;
    ((float4*)sq)[threadIdx.x] = ((const float4*)(g_combined + (size_t)b * 2 * ND + ND))[threadIdx.x];
    __syncthreads();
    int l = blockIdx.x * 8 + warp;
    size_t row = ((size_t)(b * NL + l)) * ND;
    const float4* c4 = (const float4*)(ctx + row);
    uint2* h2 = (uint2*)(g_ctxh + row);          // uint2 = 4 halves
    const float4* s4 = (const float4*)sq;
    float acc = 0.f;
#pragma unroll
    for (int k = 0; k < 8; k++) {
        int i = k * 32 + lane;
        float4 cv = c4[i], qv = s4[i];
        acc += cv.x * qv.x + cv.y * qv.y + cv.z * qv.z + cv.w * qv.w;
        union { __half2 h[2]; uint2 u; } pk;
        pk.h[0] = __floats2half2_rn(cv.x, cv.y);
        pk.h[1] = __floats2half2_rn(cv.z, cv.w);
        h2[i] = pk.u;
    }
#pragma unroll
    for (int o = 16; o > 0; o >>= 1) acc += __shfl_down_sync(0xffffffffu, acc, o);
    if (lane == 0) g_scores[b * NL + l] = acc;
}

// ---------------- C: softmax + expmap0/project (aw), bt ----------------
__global__ void kC(const float* __restrict__ dt, const float* __restrict__ cp,
                   const float* __restrict__ ab, float* __restrict__ out_aw) {
    __shared__ float s32[32];
    int b = blockIdx.x, t = threadIdx.x;
    float c = cp[0], sc = sqrtf(c);
    float maxn = (1.0f - PROJ_EPS) / sc;

    float s = g_scores[b * NL + t];
    float mx = bmax1024(s, s32);
    float e = expf(s - mx);
    float sum = bsum1024(e, s32);
    float aw = e / sum;

    float n = fmaxf(sqrtf(bsum1024(aw * aw, s32)), EPSF);
    float awh = tanhf(sc * n) / (sc * n) * aw;
    float nh = fmaxf(sqrtf(bsum1024(awh * awh, s32)), EPSF);
    if (nh > maxn) awh *= maxn / nh;
    g_aw[b * NL + t] = awh;
    out_aw[b * NL + t] = awh;

    float braw = expf(-ab[b] * dt[b * NL + t]);
    float bn = fmaxf(sqrtf(bsum1024(braw * braw, s32)), EPSF);
    float bth = tanhf(sc * bn) / (sc * bn) * braw;
    float bh = fmaxf(sqrtf(bsum1024(bth * bth, s32)), EPSF);
    if (bh > maxn) bth *= maxn / bh;
    g_bt[b * NL + t] = bth;
    if (t == 0) g_btn[b] = fminf(bh, maxn);
}

// ---------------- D1: partial column stats from fp16 ctx (512 thr x half2, descending b) ----
__global__ void __launch_bounds__(512) kD1() {
    __shared__ float sc1[CH_D], sc2[CH_D], sc3[CH_D];
    int b = NB - 1 - blockIdx.y;       // reverse: reuse L2 tail from kB
    int s = blockIdx.x, t = threadIdx.x;
    int l0 = s * CH_D;
    if (t < CH_D) {
        float a = g_aw[b * NL + l0 + t];
        float bt = g_bt[b * NL + l0 + t];
        float a2 = a * a;
        sc1[t] = a2;
        sc2[t] = a2 * bt * bt;
        sc3[t] = a2 * bt;
    }
    __syncthreads();
    const __half2* cb = (const __half2*)(g_ctxh + ((size_t)(b * NL + l0)) * ND) + t;

    float2 sx2 = {0,0}, swx2 = {0,0};
    float2 s2p = {0,0}, s2n = {0,0}, sxp = {0,0}, sxn = {0,0};

#pragma unroll 4
    for (int ll = 0; ll < CH_D; ll++) {
        float2 x = __half22float2(cb[(size_t)ll * (ND / 2)]);
        float c1 = sc1[ll], c2 = sc2[ll], c3 = sc3[ll];
        {
            float x2 = x.x * x.x; float xp = (x.x > 0.f) ? x2 : 0.f; float xm = x2 - xp;
            sx2.x += x2; swx2.x = fmaf(c1, x2, swx2.x);
            s2p.x = fmaf(c2, xp, s2p.x); s2n.x = fmaf(c2, xm, s2n.x);
            sxp.x = fmaf(c3, xp, sxp.x); sxn.x = fmaf(c3, xm, sxn.x);
        }
        {
            float x2 = x.y * x.y; float xp = (x.y > 0.f) ? x2 : 0.f; float xm = x2 - xp;
            sx2.y += x2; swx2.y = fmaf(c1, x2, swx2.y);
            s2p.y = fmaf(c2, xp, s2p.y); s2n.y = fmaf(c2, xm, s2n.y);
            sxp.y = fmaf(c3, xp, sxp.y); sxn.y = fmaf(c3, xm, sxn.y);
        }
    }
    size_t base = ((size_t)(b * SPLIT + s)) * ND;
    size_t stride = (size_t)NB * SPLIT * ND;
    ((float2*)(g_part + 0 * stride + base))[t] = sx2;
    ((float2*)(g_part + 1 * stride + base))[t] = swx2;
    ((float2*)(g_part + 2 * stride + base))[t] = s2p;
    ((float2*)(g_part + 3 * stride + base))[t] = s2n;
    ((float2*)(g_part + 4 * stride + base))[t] = sxp;
    ((float2*)(g_part + 5 * stride + base))[t] = sxn;
}

// ---------------- Df: finalize per-(b,d) scalars u, v, delta ----------------
__global__ void kDf(const float* __restrict__ cp, const float* __restrict__ ae) {
    int b = blockIdx.y;
    int d = blockIdx.x * 256 + threadIdx.x;
    size_t stride = (size_t)NB * SPLIT * ND;
    float sx2 = 0.f, swx2 = 0.f, s2p = 0.f, s2n = 0.f, sxp = 0.f, sxn = 0.f;
#pragma unroll
    for (int s = 0; s < SPLIT; s++) {
        size_t base = ((size_t)(b * SPLIT + s)) * ND + d;
        sx2  += g_part[0 * stride + base];
        swx2 += g_part[1 * stride + base];
        s2p  += g_part[2 * stride + base];
        s2n  += g_part[3 * stride + base];
        sxp  += g_part[4 * stride + base];
        sxn  += g_part[5 * stride + base];
    }

    float c = cp[0], sc = sqrtf(c);
    float maxn = (1.0f - PROJ_EPS) / sc;

    float xn   = fmaxf(sqrtf(sx2), EPSF);
    float wxnr = sqrtf(swx2);
    float wxn  = fmaxf(wxnr, EPSF);
    float s1 = tanhf(wxn / xn * artanh_c(sc * xn)) / (wxn * sc);
    float n1 = fmaxf(fabsf(s1) * wxnr, EPSF);
    float alpha = s1 * (n1 > maxn ? maxn / n1 : 1.0f);
    float nmixr = fabsf(alpha) * wxnr;

    float aeb = ae[b];
    float xn7 = fmaxf(nmixr, EPSF);
    float wxn7 = fmaxf(fabsf(aeb) * nmixr, EPSF);
    float t7 = tanhf(wxn7 / xn7 * artanh_c(sc * xn7)) / (wxn7 * sc);
    float n7 = fmaxf(fabsf(t7 * aeb) * nmixr, EPSF);
    float T = t7 * aeb * alpha * (n7 > maxn ? maxn / n7 : 1.0f);

    float m8r = sqrtf(s2p + s2n);
    float xn8 = g_btn[b];
    float wxn8 = fmaxf(fabsf(T) * m8r, EPSF);
    float t8 = tanhf(wxn8 / xn8 * artanh_c(sc * xn8)) / (wxn8 * sc);
    float dpre = t8 * T;
    float n8 = fmaxf(fabsf(dpre) * m8r, EPSF);
    float dl = dpre * (n8 > maxn ? maxn / n8 : 1.0f);

    float x2 = alpha * alpha * swx2;
    bool pos = (dl > 0.f);
    float S2 = pos ? s2p : s2n;
    float SX = pos ? sxp : sxn;
    float y2 = dl * dl * S2;
    float xy = alpha * dl * SX;
    float A  = 1.0f + 2.0f * c * xy + c * y2;
    float Bc = 1.0f - c * x2;
    float den = fmaxf(1.0f + 2.0f * c * xy + c * c * x2 * y2, EPSF);
    float nn2 = (A * A * x2 + 2.0f * A * Bc * xy + Bc * Bc * y2) / (den * den);
    float n10 = fmaxf(sqrtf(fmaxf(nn2, 0.f)), EPSF);
    float p10 = (n10 > maxn) ? maxn / n10 : 1.0f;

    g_u[b * ND + d]  = p10 * A * alpha / den;
    g_v[b * ND + d]  = p10 * Bc * dl / den;
    g_dl[b * ND + d] = dl;
}

// ---------------- E (fused): lambda + nom from fp16 ctx, 4 rows/barrier + prefetch ---------
// 256 threads own the whole 1024-d row (4 cols via uint2). Double-buffered warp sums,
// one barrier per FOUR rows; next 4 rows prefetched before the barrier.
__global__ void __launch_bounds__(256) kE(const float* __restrict__ cp) {
    __shared__ float saw[CH_E], sbt[CH_E];
    __shared__ float swsum[2][4][8];    // [buf][row][warp]
    int b = blockIdx.y;                 // ascending: reuse L2 tail from kD1
    int s = blockIdx.x, t = threadIdx.x;
    int warp = t >> 5, lane = t & 31;
    int l0 = s * CH_E;
    if (t < CH_E) { saw[t] = g_aw[b * NL + l0 + t]; sbt[t] = g_bt[b * NL + l0 + t]; }
    float c = cp[0];
    const uint2* cb = (const uint2*)(g_ctxh + ((size_t)(b * NL + l0)) * ND) + t;
    float4 u  = ((const float4*)(g_u  + (size_t)b * ND))[t];
    float4 v  = ((const float4*)(g_v  + (size_t)b * ND))[t];
    float4 dl = ((const float4*)(g_dl + (size_t)b * ND))[t];
    __syncthreads();

    float4 nom = {0, 0, 0, 0};
    uint2 r0 = cb[0];
    uint2 r1 = cb[1 * (ND / 4)];
    uint2 r2 = cb[2 * (ND / 4)];
    uint2 r3 = cb[3 * (ND / 4)];
    for (int ll = 0; ll < CH_E; ll += 4) {
        // prefetch the NEXT 4 rows before any dependent work / barrier
        uint2 p0, p1, p2, p3;
        if (ll + 4 < CH_E) {
            p0 = cb[(size_t)(ll + 4) * (ND / 4)];
            p1 = cb[(size_t)(ll + 5) * (ND / 4)];
            p2 = cb[(size_t)(ll + 6) * (ND / 4)];
            p3 = cb[(size_t)(ll + 7) * (ND / 4)];
        } else { p0 = make_uint2(0, 0); p1 = p0; p2 = p0; p3 = p0; }

        float4 x0, x1, x2, x3;
        {
            float2 h0 = __half22float2(*(__half2*)&r0.x), h1 = __half22float2(*(__half2*)&r0.y);
            x0 = make_float4(h0.x, h0.y, h1.x, h1.y);
            h0 = __half22float2(*(__half2*)&r1.x); h1 = __half22float2(*(__half2*)&r1.y);
            x1 = make_float4(h0.x, h0.y, h1.x, h1.y);
            h0 = __half22float2(*(__half2*)&r2.x); h1 = __half22float2(*(__half2*)&r2.y);
            x2 = make_float4(h0.x, h0.y, h1.x, h1.y);
            h0 = __half22float2(*(__half2*)&r3.x); h1 = __half22float2(*(__half2*)&r3.y);
            x3 = make_float4(h0.x, h0.y, h1.x, h1.y);
        }
        float a0 = saw[ll],   bt0 = sbt[ll];
        float a1 = saw[ll+1], bt1 = sbt[ll+1];
        float a2 = saw[ll+2], bt2 = sbt[ll+2];
        float a3 = saw[ll+3], bt3 = sbt[ll+3];
        float4 m0, m1, m2, m3;
        float g;
        g = a0 * bt0 * x0.x; m0.x = u.x * a0 * x0.x + ((dl.x * g) > 0.f ? v.x * g : 0.f);
        g = a0 * bt0 * x0.y; m0.y = u.y * a0 * x0.y + ((dl.y * g) > 0.f ? v.y * g : 0.f);
        g = a0 * bt0 * x0.z; m0.z = u.z * a0 * x0.z + ((dl.z * g) > 0.f ? v.z * g : 0.f);
        g = a0 * bt0 * x0.w; m0.w = u.w * a0 * x0.w + ((dl.w * g) > 0.f ? v.w * g : 0.f);
        g = a1 * bt1 * x1.x; m1.x = u.x * a1 * x1.x + ((dl.x * g) > 0.f ? v.x * g : 0.f);
        g = a1 * bt1 * x1.y; m1.y = u.y * a1 * x1.y + ((dl.y * g) > 0.f ? v.y * g : 0.f);
        g = a1 * bt1 * x1.z; m1.z = u.z * a1 * x1.z + ((dl.z * g) > 0.f ? v.z * g : 0.f);
        g = a1 * bt1 * x1.w; m1.w = u.w * a1 * x1.w + ((dl.w * g) > 0.f ? v.w * g : 0.f);
        g = a2 * bt2 * x2.x; m2.x = u.x * a2 * x2.x + ((dl.x * g) > 0.f ? v.x * g : 0.f);
        g = a2 * bt2 * x2.y; m2.y = u.y * a2 * x2.y + ((dl.y * g) > 0.f ? v.y * g : 0.f);
        g = a2 * bt2 * x2.z; m2.z = u.z * a2 * x2.z + ((dl.z * g) > 0.f ? v.z * g : 0.f);
        g = a2 * bt2 * x2.w; m2.w = u.w * a2 * x2.w + ((dl.w * g) > 0.f ? v.w * g : 0.f);
        g = a3 * bt3 * x3.x; m3.x = u.x * a3 * x3.x + ((dl.x * g) > 0.f ? v.x * g : 0.f);
        g = a3 * bt3 * x3.y; m3.y = u.y * a3 * x3.y + ((dl.y * g) > 0.f ? v.y * g : 0.f);
        g = a3 * bt3 * x3.z; m3.z = u.z * a3 * x3.z + ((dl.z * g) > 0.f ? v.z * g : 0.f);
        g = a3 * bt3 * x3.w; m3.w = u.w * a3 * x3.w + ((dl.w * g) > 0.f ? v.w * g : 0.f);

        float ss0 = m0.x * m0.x + m0.y * m0.y + m0.z * m0.z + m0.w * m0.w;
        float ss1 = m1.x * m1.x + m1.y * m1.y + m1.z * m1.z + m1.w * m1.w;
        float ss2 = m2.x * m2.x + m2.y * m2.y + m2.z * m2.z + m2.w * m2.w;
        float ss3 = m3.x * m3.x + m3.y * m3.y + m3.z * m3.z + m3.w * m3.w;
#pragma unroll
        for (int o = 16; o > 0; o >>= 1) {
            ss0 += __shfl_xor_sync(0xffffffffu, ss0, o);
            ss1 += __shfl_xor_sync(0xffffffffu, ss1, o);
            ss2 += __shfl_xor_sync(0xffffffffu, ss2, o);
            ss3 += __shfl_xor_sync(0xffffffffu, ss3, o);
        }
        int buf = (ll >> 2) & 1;
        if (lane == 0) {
            swsum[buf][0][warp] = ss0;
            swsum[buf][1][warp] = ss1;
            swsum[buf][2][warp] = ss2;
            swsum[buf][3][warp] = ss3;
        }
        __syncthreads();
        float tot0 = 0.f, tot1 = 0.f, tot2 = 0.f, tot3 = 0.f;
#pragma unroll
        for (int w = 0; w < 8; w++) {
            tot0 += swsum[buf][0][w];
            tot1 += swsum[buf][1][w];
            tot2 += swsum[buf][2][w];
            tot3 += swsum[buf][3][w];
        }
        float lam0 = 2.0f / fmaxf(1.0f - c * tot0, EPSF);
        float lam1 = 2.0f / fmaxf(1.0f - c * tot1, EPSF);
        float lam2 = 2.0f / fmaxf(1.0f - c * tot2, EPSF);
        float lam3 = 2.0f / fmaxf(1.0f - c * tot3, EPSF);
        nom.x = fmaf(lam0, m0.x, fmaf(lam1, m1.x, fmaf(lam2, m2.x, fmaf(lam3, m3.x, nom.x))));
        nom.y = fmaf(lam0, m0.y, fmaf(lam1, m1.y, fmaf(lam2, m2.y, fmaf(lam3, m3.y, nom.y))));
        nom.z = fmaf(lam0, m0.z, fmaf(lam1, m1.z, fmaf(lam2, m2.z, fmaf(lam3, m3.z, nom.z))));
        nom.w = fmaf(lam0, m0.w, fmaf(lam1, m1.w, fmaf(lam2, m2.w, fmaf(lam3, m3.w, nom.w))));
        if (t == 0) {
            g_lam[b * NL + l0 + ll]     = lam0;
            g_lam[b * NL + l0 + ll + 1] = lam1;
            g_lam[b * NL + l0 + ll + 2] = lam2;
            g_lam[b * NL + l0 + ll + 3] = lam3;
        }
        r0 = p0; r1 = p1; r2 = p2; r3 = p3;
        // no second barrier: next iteration writes the other buffer.
    }
    ((float4*)(g_nomp + ((size_t)(b * SPLITE + s)) * ND))[t] = nom;
}

// ---------------- F: midpoint epilogue ----------------
__global__ void kF(const float* __restrict__ cp) {
    __shared__ float s32[32];
    int b = blockIdx.x, t = threadIdx.x;
    float c = cp[0], sc = sqrtf(c);
    float lam = g_lam[b * NL + t];
    float den = bsum1024(lam - 1.0f, s32);
    den = (den >= 0.f) ? fmaxf(den, 1e-10f) : fminf(den, -1e-10f);

    float nom = 0.f;
#pragma unroll
    for (int s = 0; s < SPLITE; s++)
        nom += g_nomp[((size_t)(b * SPLITE + s)) * ND + t];

    float tm = nom / den;
    float nr = sqrtf(bsum1024(tm * tm, s32));
    float n = fmaxf(nr, EPSF);
    float cf = tanhf(0.5f * artanh_c(sc * n)) / (sc * n);
    float nf = fmaxf(fabsf(cf) * nr, EPSF);
    float lc = artanh_c(sc * nf) / (sc * nf);
    g_combined[(size_t)b * 2 * ND + t] = lc * cf * tm;
}

// ---------------- G: out = tanh(combined @ W_out^T) ----------------
__global__ void kG(const float* __restrict__ W_out, float* __restrict__ out) {
    int b = threadIdx.x;
    int d = blockIdx.x * 4 + threadIdx.y;
    const float4* cb4 = (const float4*)(g_combined + (size_t)b * 2 * ND);
    const float4* w4  = (const float4*)(W_out + (size_t)d * 2 * ND);
    float acc = 0.f;
#pragma unroll 4
    for (int k = 0; k < 2 * ND / 4; k++) {
        float4 a = cb4[k], w = w4[k];
        acc += a.x * w.x + a.y * w.y + a.z * w.z + a.w * w.w;
    }
    out[b * ND + d] = tanhf(acc);
}

// ---------------- launch ----------------
extern "C" void kernel_launch(void* const* d_in, const int* in_sizes, int n_in,
                              void* d_out, int out_size) {
    const float* query = (const float*)d_in[0];
    const float* ctx   = (const float*)d_in[1];
    const float* dt    = (const float*)d_in[2];
    const float* cp    = (const float*)d_in[3];
    const float* W_in  = (const float*)d_in[4];
    const float* W_out = (const float*)d_in[5];
    const float* ae    = (const float*)d_in[6];
    const float* ab    = (const float*)d_in[7];
    float* out = (float*)d_out;

    kA <<<ND / 4, dim3(64, 4)>>>(query, W_in);
    kB <<<dim3(NL / 8, NB), 256>>>(ctx);
    kC <<<NB, 1024>>>(dt, cp, ab, out + NB * ND);
    kD1<<<dim3(SPLIT, NB), 512>>>();
    kDf<<<dim3(ND / 256, NB), 256>>>(cp, ae);
    kE <<<dim3(SPLITE, NB), 256>>>(cp);
    kF <<<NB, 1024>>>(cp);
    kG <<<ND / 4, dim3(64, 4)>>>(W_out, out);
}